// round 4
// baseline (speedup 1.0000x reference)
#include <cuda_runtime.h>

// P1 vector FEM eval on structured 16x16 triangulated unit square,
// bit-faithful to the JAX reference in exact fp32:
//
// Classification (per reference, all arithmetic fp32, products by +-16 exact):
//   P  = fl(16px - 16py)
//   T1(lower): s1 = fl(P - (i-j)),  t1 = v = 16py - j (exact Sterbenz)
//   T2(upper): s2 = u = 16px - i (exact),  t2 = -s1 (bitwise)
//   inX = sX > -1e-10f && tX > -1e-10f && fl(sX+tX) < 1.0f   (f32(1+1e-10)==1)
//   argmax picks highest triangle index -> T2 wins ties.
//   bbox: bounds (k/16 -+ 1e-10) round back to exactly k/16 in f32, strict
//   compare -> a point EXACTLY on an interior gridline is in NO bbox -> out=0.
//
// Value (reference op order, no FMA contraction):
//   T1: s=fl(u-v), t=v ;  T2: s=u, t=fl(v-u)
//   b0 = fl(fl(1-s)-t);  out = fl(fl(fl(b0*w0)+fl(s*w1))+fl(t*w2))
//
// Inputs: x[4,16384,2], weight_x[289], weight_y[289], (Minv,A,bbox,dofs unused)
// Output: float32 [4,16384,2]

__global__ void __launch_bounds__(256)
p1_eval_kernel(const float2* __restrict__ pts,
               const float*  __restrict__ wx,
               const float*  __restrict__ wy,
               float2* __restrict__ out,
               int n_pts)
{
    int idx = blockIdx.x * blockDim.x + threadIdx.x;
    if (idx >= n_pts) return;

    float2 p = pts[idx];
    const float NTOL = -1e-10f;

    float fx = __fmul_rn(p.x, 16.0f);   // exact (power-of-2 scale)
    float fy = __fmul_rn(p.y, 16.0f);
    int i = (int)floorf(fx);
    int j = (int)floorf(fy);
    i = min(max(i, 0), 15);
    j = min(max(j, 0), 15);

    float u = __fsub_rn(fx, (float)i);  // exact
    float v = __fsub_rn(fy, (float)j);  // exact

    // --- reference-faithful inside tests (exact fp32) ---
    float P  = __fsub_rn(fx, fy);                    // fl(16px - 16py)
    float s1 = __fsub_rn(P, (float)(i - j));         // T1 s
    float t1 = v;                                    // T1 t
    float s2 = u;                                    // T2 s
    float t2 = -s1;                                  // T2 t (bitwise)

    bool in1 = (s1 > NTOL) && (t1 > NTOL) && (__fadd_rn(s1, t1) < 1.0f);
    bool in2 = (s2 > NTOL) && (t2 > NTOL) && (__fadd_rn(s2, t2) < 1.0f);

    // --- bbox: strict compares vs exact k/16 bounds ---
    // interior gridline points (px == i/16, i>=1, or py == j/16, j>=1) fail
    // every cell's bbox in the reference -> output 0
    bool on_gx = (u == 0.0f) && (i > 0);
    bool on_gy = (v == 0.0f) && (j > 0);
    bool in_domain = (p.x >= 0.0f) && (p.x < 1.0f) &&
                     (p.y >= 0.0f) && (p.y < 1.0f);
    bool hit = in_domain && !on_gx && !on_gy && (in1 || in2);

    // --- value: reference op order, argmax tie -> T2 ---
    int v00 = i * 17 + j;
    float s, t;
    int k1, k2;
    if (in2) {
        s = u;
        t = __fsub_rn(v, u);
        k1 = v00 + 18; k2 = v00 + 1;     // (v00, v11, v01)
    } else {
        s = __fsub_rn(u, v);
        t = v;
        k1 = v00 + 17; k2 = v00 + 18;    // (v00, v10, v11)
    }
    float b0 = __fsub_rn(__fsub_rn(1.0f, s), t);

    float w0x = __ldg(wx + v00), w1x = __ldg(wx + k1), w2x = __ldg(wx + k2);
    float w0y = __ldg(wy + v00), w1y = __ldg(wy + k1), w2y = __ldg(wy + k2);

    float ox = __fadd_rn(__fadd_rn(__fmul_rn(b0, w0x), __fmul_rn(s, w1x)),
                         __fmul_rn(t, w2x));
    float oy = __fadd_rn(__fadd_rn(__fmul_rn(b0, w0y), __fmul_rn(s, w1y)),
                         __fmul_rn(t, w2y));

    out[idx] = hit ? make_float2(ox, oy) : make_float2(0.0f, 0.0f);
}

extern "C" void kernel_launch(void* const* d_in, const int* in_sizes, int n_in,
                              void* d_out, int out_size)
{
    const float2* pts = (const float2*)d_in[0];
    const float*  wx  = (const float*)d_in[1];
    const float*  wy  = (const float*)d_in[2];
    float2* out = (float2*)d_out;

    int n_pts = in_sizes[0] / 2;   // 4*16384 = 65536
    int threads = 256;
    int blocks = (n_pts + threads - 1) / threads;
    p1_eval_kernel<<<blocks, threads>>>(pts, wx, wy, out, n_pts);
}